// round 13
// baseline (speedup 1.0000x reference)
#include <cuda_runtime.h>
#include <cuda_fp16.h>
#include <cstdint>

// StyleGAN2 modulated+demodulated conv on GB300 (sm_103 base target -> HMMA).
// x: (8,128,128,128) NHWC fp32, style: (8,128), kernel: (3,3,128,128) -> NHWC fp32
//
// Single-product fp16 GEMM: Y = fp16(X) * fp16(W_mod_demod), fp32 accum.
// K0 split_x: X fp32 -> fp16
// K1 wprep  : demod scale + modulate -> fp16 W, layout [b][f][k]
// K2 gemm   : per (h,b) CTA: M=128 (w), N=128 (f), K=1152.
//   A from 130-row shifted windows (6 stages; 3 dx taps via smem row offset).
//   B: 18 chunks of 64, DOUBLE-buffered ring; per iter: wait(0) -> sync ->
//   issue next -> compute (issued chunk has a full compute phase to land).
//   4 warps, warp tile 64x64, smem 67.6KB -> 3 CTAs/SM (12 warps: fills the
//   tensor pipe during other warps' LDSM/barrier windows).

#define HW    128
#define CIN   128
#define FOUT  128
#define BATCH 8
#define KK    1152
#define NCH   18

__device__ __half g_xh[BATCH * HW * HW * CIN];
__device__ __half g_wh[BATCH * FOUT * KK];

// ---------------- asm helpers ----------------
__device__ __forceinline__ uint32_t smem_u32(const void* p) {
    uint32_t a;
    asm("{ .reg .u64 t; cvta.to.shared.u64 t, %1; cvt.u32.u64 %0, t; }"
        : "=r"(a) : "l"(p));
    return a;
}
__device__ __forceinline__ void ldsm4(uint32_t* r, uint32_t addr) {
    asm volatile("ldmatrix.sync.aligned.m8n8.x4.shared.b16 {%0,%1,%2,%3}, [%4];"
                 : "=r"(r[0]), "=r"(r[1]), "=r"(r[2]), "=r"(r[3]) : "r"(addr));
}
__device__ __forceinline__ void mma_f16(float* c, const uint32_t* a, const uint32_t* b) {
    asm volatile(
        "mma.sync.aligned.m16n8k16.row.col.f32.f16.f16.f32 "
        "{%0,%1,%2,%3}, {%4,%5,%6,%7}, {%8,%9}, {%0,%1,%2,%3};"
        : "+f"(c[0]), "+f"(c[1]), "+f"(c[2]), "+f"(c[3])
        : "r"(a[0]), "r"(a[1]), "r"(a[2]), "r"(a[3]), "r"(b[0]), "r"(b[1]));
}
__device__ __forceinline__ void cp_async16z(uint32_t saddr, const void* gaddr,
                                            uint32_t src_size) {
    asm volatile("cp.async.cg.shared.global [%0], [%1], 16, %2;"
                 :: "r"(saddr), "l"(gaddr), "r"(src_size));
}
__device__ __forceinline__ void cp_async16(uint32_t saddr, const void* gaddr) {
    asm volatile("cp.async.cg.shared.global [%0], [%1], 16;"
                 :: "r"(saddr), "l"(gaddr));
}
__device__ __forceinline__ void cp_commit() { asm volatile("cp.async.commit_group;"); }
#define CP_WAIT(n) asm volatile("cp.async.wait_group %0;" :: "n"(n) : "memory")

// ---------------------------------------------------------------------------
// K0: X fp32 -> fp16 (8 floats/thread).
// ---------------------------------------------------------------------------
__global__ void split_x_kernel(const float* __restrict__ X) {
    size_t i = ((size_t)blockIdx.x * 256 + threadIdx.x) * 8;
    float4 v0 = *(const float4*)(X + i);
    float4 v1 = *(const float4*)(X + i + 4);
    __half2 h01 = __floats2half2_rn(v0.x, v0.y);
    __half2 h23 = __floats2half2_rn(v0.z, v0.w);
    __half2 h45 = __floats2half2_rn(v1.x, v1.y);
    __half2 h67 = __floats2half2_rn(v1.z, v1.w);
    uint4 o = make_uint4(*(uint32_t*)&h01, *(uint32_t*)&h23,
                         *(uint32_t*)&h45, *(uint32_t*)&h67);
    *(uint4*)(g_xh + i) = o;
}

// ---------------------------------------------------------------------------
// K1: fused demod scale + modulate -> fp16, layout [b][f][k].
// ---------------------------------------------------------------------------
__global__ void wprep_kernel(const float* __restrict__ style,
                             const float* __restrict__ kern) {
    const int f = blockIdx.x, b = blockIdx.y, c = threadIdx.x;
    const float st = style[b * CIN + c] + 1.0f;
    float wv[9];
    float ss = 0.0f;
    #pragma unroll
    for (int p = 0; p < 9; ++p) {
        float w = kern[(p * 128 + c) * 128 + f] * st;
        wv[p] = w;
        ss = fmaf(w, w, ss);
    }
    __shared__ float red[128];
    red[c] = ss;
    __syncthreads();
    #pragma unroll
    for (int s = 64; s > 0; s >>= 1) {
        if (c < s) red[c] += red[c + s];
        __syncthreads();
    }
    const float scale = rsqrtf(red[0] + 1e-8f);
    const size_t base = (size_t)(b * 128 + f) * KK;
    #pragma unroll
    for (int p = 0; p < 9; ++p)
        g_wh[base + p * 128 + c] = __float2half_rn(wv[p] * scale);
}

// ---------------------------------------------------------------------------
// K2: HMMA implicit GEMM with shifted-window A, occ 3.
// grid (128 h, 8 b) x 128 threads (4 warps), 3 CTAs/SM.
// Warps 2(m) x 2(n), warp tile 64x64.
// SMEM: A windows 2 x 17408 (130 rows x 128B, SW128), B 2 x 16384 = 67584.
// ---------------------------------------------------------------------------
#define ABUF_BYTES 17408
#define BBUF_BYTES 16384
#define SMEM_B0    (2 * ABUF_BYTES)               // 34816
#define SMEM_TOTAL (SMEM_B0 + 2 * BBUF_BYTES)     // 67584

__global__ __launch_bounds__(128, 3)
void mdconv_hmma_kernel(float* __restrict__ Y) {
    extern __shared__ __align__(1024) char smem[];
    const uint32_t sb  = smem_u32(smem);
    const int tid  = threadIdx.x;
    const int wid  = tid >> 5;
    const int lane = tid & 31;
    const int h = blockIdx.x;
    const int b = blockIdx.y;

    const int mw = (wid >> 1) * 64;     // warp m offset
    const int nw = (wid & 1) * 64;      // warp n offset

    const __half* xh_b = g_xh + (size_t)b * HW * HW * CIN;
    const __half* wh_b = g_wh + (size_t)b * FOUT * KK;

    // ---- ldmatrix per-lane invariants ----
    const int arow_l = (lane & 7) + ((lane >> 3) & 1) * 8;
    const int akb_l  = ((lane >> 4) & 1) * 16;
    const int brow_l = (lane & 7) + ((lane >> 4) & 1) * 8;
    const int bkb_l  = ((lane >> 3) & 1) * 16;

    int aRowBase[4];
    #pragma unroll
    for (int mt = 0; mt < 4; ++mt) aRowBase[mt] = mw + mt * 16 + arow_l;
    uint32_t bRowOff[4], bXor[4];
    #pragma unroll
    for (int np = 0; np < 4; ++np) {
        const int row = nw + np * 16 + brow_l;
        bRowOff[np] = (uint32_t)row * 128;
        bXor[np]    = (uint32_t)((row & 7) * 16);
    }

    float acc[4][8][4];
    #pragma unroll
    for (int i = 0; i < 4; ++i)
        #pragma unroll
        for (int j = 0; j < 8; ++j)
            #pragma unroll
            for (int q = 0; q < 4; ++q) acc[i][j][q] = 0.0f;

    // A window for stage s_: 130 rows (w=-1..128) x 64 ch of X[h+dy][.][c0..]
    #define ISSUE_A(s_)                                                       \
    {                                                                         \
        const uint32_t abuf = sb + (uint32_t)((s_) & 1) * ABUF_BYTES;         \
        const int dy_ = (s_) / 2 - 1;                                         \
        const int c0_ = ((s_) & 1) * 64;                                      \
        const int hh_ = h + dy_;                                              \
        const bool hok_ = (unsigned)hh_ < HW;                                 \
        _Pragma("unroll")                                                     \
        for (int t = 0; t < 8; ++t) {                                         \
            const int u = tid + 128 * t;                                      \
            const int row = u >> 3, seg = u & 7;                              \
            const int wq = row - 1;                                           \
            const bool ok = hok_ && ((unsigned)wq < HW);                      \
            const __half* ga = ok                                             \
                ? xh_b + (((size_t)hh_ * HW + wq) << 7) + c0_ + seg * 8       \
                : xh_b;                                                       \
            cp_async16z(abuf + row * 128 + ((seg * 16) ^ ((row & 7) * 16)),   \
                        ga, ok ? 16u : 0u);                                   \
        }                                                                     \
        if (tid < 16) {                                                       \
            const int u = 1024 + tid;                                         \
            const int row = u >> 3, seg = u & 7;                              \
            const int wq = row - 1;                                           \
            const bool ok = hok_ && ((unsigned)wq < HW);                      \
            const __half* ga = ok                                             \
                ? xh_b + (((size_t)hh_ * HW + wq) << 7) + c0_ + seg * 8       \
                : xh_b;                                                       \
            cp_async16z(abuf + row * 128 + ((seg * 16) ^ ((row & 7) * 16)),   \
                        ga, ok ? 16u : 0u);                                   \
        }                                                                     \
    }

    #define ISSUE_B(kc_)                                                      \
    {                                                                         \
        const uint32_t bbuf = sb + SMEM_B0                                    \
                            + (uint32_t)((kc_) & 1) * BBUF_BYTES;             \
        const int s_  = (kc_) / 3;                                            \
        const int p_  = (s_ / 2) * 3 + (kc_) % 3;                             \
        const int c0_ = (s_ & 1) * 64;                                        \
        _Pragma("unroll")                                                     \
        for (int t = 0; t < 8; ++t) {                                         \
            const int u = tid + 128 * t;                                      \
            const int f_ = u >> 3, seg = u & 7;                               \
            cp_async16(bbuf + f_ * 128 + ((seg * 16) ^ ((f_ & 7) * 16)),      \
                       wh_b + (size_t)f_ * KK + p_ * 128 + c0_ + seg * 8);    \
        }                                                                     \
    }

    // ---- prologue: group {A0, B0} ----
    ISSUE_A(0); ISSUE_B(0); cp_commit();

    for (int kc = 0; kc < NCH; ++kc) {
        // wait(0): B(kc) (issued last iteration, a full compute phase ago)
        // and any pending A window complete.
        CP_WAIT(0);
        __syncthreads();

        const int s    = kc / 3;
        const int dxp1 = kc % 3;

        // Issue next chunk AFTER the barrier (the sync fences last iteration's
        // reads of the buffer being overwritten: B buf (kc+1)&1 was last read
        // in compute(kc-1); A buf (s+1)&1 was last read in compute(3s-1)).
        if (kc % 3 == 0 && (s + 1) < 6) ISSUE_A(s + 1);
        if (kc + 1 < NCH) ISSUE_B(kc + 1);
        cp_commit();

        const uint32_t abuf = sb + (uint32_t)(s & 1) * ABUF_BYTES;
        const uint32_t bbuf = sb + SMEM_B0 + (uint32_t)(kc & 1) * BBUF_BYTES;

        #pragma unroll
        for (int ks = 0; ks < 4; ++ks) {
            uint32_t Af[4][4], Bf[4][4];
            #pragma unroll
            for (int mt = 0; mt < 4; ++mt) {
                const int row = aRowBase[mt] + dxp1;
                const uint32_t off = (uint32_t)row * 128
                    + ((uint32_t)(ks * 32 + akb_l) ^ ((row & 7) * 16));
                ldsm4(Af[mt], abuf + off);
            }
            #pragma unroll
            for (int np = 0; np < 4; ++np)
                ldsm4(Bf[np], bbuf + bRowOff[np]
                      + ((uint32_t)(ks * 32 + bkb_l) ^ bXor[np]));
            #pragma unroll
            for (int mt = 0; mt < 4; ++mt)
                #pragma unroll
                for (int np = 0; np < 4; ++np) {
                    mma_f16(acc[mt][np * 2],     Af[mt], &Bf[np][0]);
                    mma_f16(acc[mt][np * 2 + 1], Af[mt], &Bf[np][2]);
                }
        }
    }

    // ---- epilogue: direct STG ----
    float* Yb = Y + (((size_t)b * HW + h) * HW) * FOUT;
    #pragma unroll
    for (int mt = 0; mt < 4; ++mt)
        #pragma unroll
        for (int rg = 0; rg < 2; ++rg) {
            const int m = mw + mt * 16 + rg * 8 + (lane >> 2);
            float* yr = Yb + (size_t)m * FOUT + nw + (lane & 3) * 2;
            #pragma unroll
            for (int nt = 0; nt < 8; ++nt) {
                float2 v;
                v.x = acc[mt][nt][rg * 2];
                v.y = acc[mt][nt][rg * 2 + 1];
                *(float2*)(yr + nt * 8) = v;
            }
        }
    #undef ISSUE_A
    #undef ISSUE_B
}

// ---------------------------------------------------------------------------
extern "C" void kernel_launch(void* const* d_in, const int* in_sizes, int n_in,
                              void* d_out, int out_size) {
    const float* x     = (const float*)d_in[0];   // (8,128,128,128)
    const float* style = (const float*)d_in[1];   // (8,128)
    const float* kern  = (const float*)d_in[2];   // (3,3,128,128)
    float* y = (float*)d_out;

    cudaFuncSetAttribute(mdconv_hmma_kernel,
                         cudaFuncAttributeMaxDynamicSharedMemorySize, SMEM_TOTAL);

    split_x_kernel<<<(BATCH * HW * HW * CIN) / 8 / 256, 256>>>(x);
    wprep_kernel<<<dim3(FOUT, BATCH), 128>>>(style, kern);
    mdconv_hmma_kernel<<<dim3(HW, BATCH), 128, SMEM_TOTAL>>>(y);
}

// round 14
// speedup vs baseline: 1.1455x; 1.1455x over previous
#include <cuda_runtime.h>
#include <cuda_fp16.h>
#include <cstdint>

// StyleGAN2 modulated+demodulated conv on GB300 (sm_103 base target -> HMMA).
// x: (8,128,128,128) NHWC fp32, style: (8,128), kernel: (3,3,128,128) -> NHWC fp32
//
// Single-product fp16 GEMM: Y = fp16(X) * fp16(W_mod_demod), fp32 accum.
// K0 wprep  : demod scale + modulate -> fp16 W, [b][f][k] (launched FIRST:
//             its latency-bound strided loads overlap split_x's stream)
// K1 split_x: X fp32 -> fp16, 16 elems/thread (MLP 4)
// K2 gemm   : per (h,b) CTA: M=128 (w), N=128 (f), K=1152.  (R11-exact)
//   A from 130-row shifted windows (6 stages; 3 dx taps via smem row offset).
//   B: 18 chunks of 64, 4-buffer cp.async ring, wait_group(2).
//   4 warps, warp tile 64x64, 2 CTAs/SM.

#define HW    128
#define CIN   128
#define FOUT  128
#define BATCH 8
#define KK    1152
#define NCH   18

__device__ __half g_xh[BATCH * HW * HW * CIN];
__device__ __half g_wh[BATCH * FOUT * KK];

// ---------------- asm helpers ----------------
__device__ __forceinline__ uint32_t smem_u32(const void* p) {
    uint32_t a;
    asm("{ .reg .u64 t; cvta.to.shared.u64 t, %1; cvt.u32.u64 %0, t; }"
        : "=r"(a) : "l"(p));
    return a;
}
__device__ __forceinline__ void ldsm4(uint32_t* r, uint32_t addr) {
    asm volatile("ldmatrix.sync.aligned.m8n8.x4.shared.b16 {%0,%1,%2,%3}, [%4];"
                 : "=r"(r[0]), "=r"(r[1]), "=r"(r[2]), "=r"(r[3]) : "r"(addr));
}
__device__ __forceinline__ void mma_f16(float* c, const uint32_t* a, const uint32_t* b) {
    asm volatile(
        "mma.sync.aligned.m16n8k16.row.col.f32.f16.f16.f32 "
        "{%0,%1,%2,%3}, {%4,%5,%6,%7}, {%8,%9}, {%0,%1,%2,%3};"
        : "+f"(c[0]), "+f"(c[1]), "+f"(c[2]), "+f"(c[3])
        : "r"(a[0]), "r"(a[1]), "r"(a[2]), "r"(a[3]), "r"(b[0]), "r"(b[1]));
}
__device__ __forceinline__ void cp_async16z(uint32_t saddr, const void* gaddr,
                                            uint32_t src_size) {
    asm volatile("cp.async.cg.shared.global [%0], [%1], 16, %2;"
                 :: "r"(saddr), "l"(gaddr), "r"(src_size));
}
__device__ __forceinline__ void cp_async16(uint32_t saddr, const void* gaddr) {
    asm volatile("cp.async.cg.shared.global [%0], [%1], 16;"
                 :: "r"(saddr), "l"(gaddr));
}
__device__ __forceinline__ void cp_commit() { asm volatile("cp.async.commit_group;"); }
#define CP_WAIT(n) asm volatile("cp.async.wait_group %0;" :: "n"(n) : "memory")

// ---------------------------------------------------------------------------
// K1: X fp32 -> fp16, 16 elems/thread (4 independent float4 loads -> MLP 4).
// ---------------------------------------------------------------------------
__global__ void split_x_kernel(const float* __restrict__ X) {
    size_t i = ((size_t)blockIdx.x * 256 + threadIdx.x) * 16;
    float4 v0 = *(const float4*)(X + i);
    float4 v1 = *(const float4*)(X + i + 4);
    float4 v2 = *(const float4*)(X + i + 8);
    float4 v3 = *(const float4*)(X + i + 12);
    __half2 a0 = __floats2half2_rn(v0.x, v0.y);
    __half2 a1 = __floats2half2_rn(v0.z, v0.w);
    __half2 a2 = __floats2half2_rn(v1.x, v1.y);
    __half2 a3 = __floats2half2_rn(v1.z, v1.w);
    __half2 a4 = __floats2half2_rn(v2.x, v2.y);
    __half2 a5 = __floats2half2_rn(v2.z, v2.w);
    __half2 a6 = __floats2half2_rn(v3.x, v3.y);
    __half2 a7 = __floats2half2_rn(v3.z, v3.w);
    uint4 o0 = make_uint4(*(uint32_t*)&a0, *(uint32_t*)&a1,
                          *(uint32_t*)&a2, *(uint32_t*)&a3);
    uint4 o1 = make_uint4(*(uint32_t*)&a4, *(uint32_t*)&a5,
                          *(uint32_t*)&a6, *(uint32_t*)&a7);
    *(uint4*)(g_xh + i)     = o0;
    *(uint4*)(g_xh + i + 8) = o1;
}

// ---------------------------------------------------------------------------
// K0: fused demod scale + modulate -> fp16, layout [b][f][k].
// ---------------------------------------------------------------------------
__global__ void wprep_kernel(const float* __restrict__ style,
                             const float* __restrict__ kern) {
    const int f = blockIdx.x, b = blockIdx.y, c = threadIdx.x;
    const float st = style[b * CIN + c] + 1.0f;
    float wv[9];
    float ss = 0.0f;
    #pragma unroll
    for (int p = 0; p < 9; ++p) {
        float w = kern[(p * 128 + c) * 128 + f] * st;
        wv[p] = w;
        ss = fmaf(w, w, ss);
    }
    __shared__ float red[128];
    red[c] = ss;
    __syncthreads();
    #pragma unroll
    for (int s = 64; s > 0; s >>= 1) {
        if (c < s) red[c] += red[c + s];
        __syncthreads();
    }
    const float scale = rsqrtf(red[0] + 1e-8f);
    const size_t base = (size_t)(b * 128 + f) * KK;
    #pragma unroll
    for (int p = 0; p < 9; ++p)
        g_wh[base + p * 128 + c] = __float2half_rn(wv[p] * scale);
}

// ---------------------------------------------------------------------------
// K2: HMMA implicit GEMM with shifted-window A (R11-exact, verified).
// grid (128 h, 8 b) x 128 threads (4 warps), 2 CTAs/SM.
// Warps 2(m) x 2(n), warp tile 64x64.
// SMEM: A windows 2 x 17408 (130 rows x 128B, SW128), B 4 x 16384.
// ---------------------------------------------------------------------------
#define ABUF_BYTES 17408
#define BBUF_BYTES 16384
#define SMEM_B0    (2 * ABUF_BYTES)               // 34816
#define SMEM_TOTAL (SMEM_B0 + 4 * BBUF_BYTES)     // 100352

__global__ __launch_bounds__(128, 2)
void mdconv_hmma_kernel(float* __restrict__ Y) {
    extern __shared__ __align__(1024) char smem[];
    const uint32_t sb  = smem_u32(smem);
    const int tid  = threadIdx.x;
    const int wid  = tid >> 5;
    const int lane = tid & 31;
    const int h = blockIdx.x;
    const int b = blockIdx.y;

    const int mw = (wid >> 1) * 64;     // warp m offset
    const int nw = (wid & 1) * 64;      // warp n offset

    const __half* xh_b = g_xh + (size_t)b * HW * HW * CIN;
    const __half* wh_b = g_wh + (size_t)b * FOUT * KK;

    // ---- ldmatrix per-lane invariants ----
    const int arow_l = (lane & 7) + ((lane >> 3) & 1) * 8;
    const int akb_l  = ((lane >> 4) & 1) * 16;
    const int brow_l = (lane & 7) + ((lane >> 4) & 1) * 8;
    const int bkb_l  = ((lane >> 3) & 1) * 16;

    int aRowBase[4];
    #pragma unroll
    for (int mt = 0; mt < 4; ++mt) aRowBase[mt] = mw + mt * 16 + arow_l;
    uint32_t bRowOff[4], bXor[4];
    #pragma unroll
    for (int np = 0; np < 4; ++np) {
        const int row = nw + np * 16 + brow_l;
        bRowOff[np] = (uint32_t)row * 128;
        bXor[np]    = (uint32_t)((row & 7) * 16);
    }

    float acc[4][8][4];
    #pragma unroll
    for (int i = 0; i < 4; ++i)
        #pragma unroll
        for (int j = 0; j < 8; ++j)
            #pragma unroll
            for (int q = 0; q < 4; ++q) acc[i][j][q] = 0.0f;

    // A window for stage s_: 130 rows (w=-1..128) x 64 ch of X[h+dy][.][c0..]
    #define ISSUE_A(s_)                                                       \
    {                                                                         \
        const uint32_t abuf = sb + (uint32_t)((s_) & 1) * ABUF_BYTES;         \
        const int dy_ = (s_) / 2 - 1;                                         \
        const int c0_ = ((s_) & 1) * 64;                                      \
        const int hh_ = h + dy_;                                              \
        const bool hok_ = (unsigned)hh_ < HW;                                 \
        _Pragma("unroll")                                                     \
        for (int t = 0; t < 8; ++t) {                                         \
            const int u = tid + 128 * t;                                      \
            const int row = u >> 3, seg = u & 7;                              \
            const int wq = row - 1;                                           \
            const bool ok = hok_ && ((unsigned)wq < HW);                      \
            const __half* ga = ok                                             \
                ? xh_b + (((size_t)hh_ * HW + wq) << 7) + c0_ + seg * 8       \
                : xh_b;                                                       \
            cp_async16z(abuf + row * 128 + ((seg * 16) ^ ((row & 7) * 16)),   \
                        ga, ok ? 16u : 0u);                                   \
        }                                                                     \
        if (tid < 16) {                                                       \
            const int u = 1024 + tid;                                         \
            const int row = u >> 3, seg = u & 7;                              \
            const int wq = row - 1;                                           \
            const bool ok = hok_ && ((unsigned)wq < HW);                      \
            const __half* ga = ok                                             \
                ? xh_b + (((size_t)hh_ * HW + wq) << 7) + c0_ + seg * 8       \
                : xh_b;                                                       \
            cp_async16z(abuf + row * 128 + ((seg * 16) ^ ((row & 7) * 16)),   \
                        ga, ok ? 16u : 0u);                                   \
        }                                                                     \
    }

    #define ISSUE_B(kc_)                                                      \
    {                                                                         \
        const uint32_t bbuf = sb + SMEM_B0                                    \
                            + (uint32_t)((kc_) & 3) * BBUF_BYTES;             \
        const int s_  = (kc_) / 3;                                            \
        const int p_  = (s_ / 2) * 3 + (kc_) % 3;                             \
        const int c0_ = (s_ & 1) * 64;                                        \
        _Pragma("unroll")                                                     \
        for (int t = 0; t < 8; ++t) {                                         \
            const int u = tid + 128 * t;                                      \
            const int f_ = u >> 3, seg = u & 7;                               \
            cp_async16(bbuf + f_ * 128 + ((seg * 16) ^ ((f_ & 7) * 16)),      \
                       wh_b + (size_t)f_ * KK + p_ * 128 + c0_ + seg * 8);    \
        }                                                                     \
    }

    // ---- prologue: g0={A0,B0}, g1={B1}, g2={B2} ----
    ISSUE_A(0); ISSUE_B(0); cp_commit();
    ISSUE_B(1); cp_commit();
    ISSUE_B(2); cp_commit();

    for (int kc = 0; kc < NCH; ++kc) {
        // wait(2): committed groups here = 3+kc; <=2 outstanding ->
        // groups 0..kc complete -> chunk kc's B and its A window resident.
        CP_WAIT(2);
        __syncthreads();

        const int s    = kc / 3;
        const int dxp1 = kc % 3;

        // Issue AFTER the barrier (overwritten buffers were last read at
        // iteration kc-1; the barrier above fences those reads).
        if (kc % 3 == 0 && (s + 1) < 6) ISSUE_A(s + 1);
        if (kc + 3 < NCH) ISSUE_B(kc + 3);
        cp_commit();

        const uint32_t abuf = sb + (uint32_t)(s & 1) * ABUF_BYTES;
        const uint32_t bbuf = sb + SMEM_B0 + (uint32_t)(kc & 3) * BBUF_BYTES;

        #pragma unroll
        for (int ks = 0; ks < 4; ++ks) {
            uint32_t Af[4][4], Bf[4][4];
            #pragma unroll
            for (int mt = 0; mt < 4; ++mt) {
                const int row = aRowBase[mt] + dxp1;
                const uint32_t off = (uint32_t)row * 128
                    + ((uint32_t)(ks * 32 + akb_l) ^ ((row & 7) * 16));
                ldsm4(Af[mt], abuf + off);
            }
            #pragma unroll
            for (int np = 0; np < 4; ++np)
                ldsm4(Bf[np], bbuf + bRowOff[np]
                      + ((uint32_t)(ks * 32 + bkb_l) ^ bXor[np]));
            #pragma unroll
            for (int mt = 0; mt < 4; ++mt)
                #pragma unroll
                for (int np = 0; np < 4; ++np) {
                    mma_f16(acc[mt][np * 2],     Af[mt], &Bf[np][0]);
                    mma_f16(acc[mt][np * 2 + 1], Af[mt], &Bf[np][2]);
                }
        }
    }

    // ---- epilogue: direct STG ----
    float* Yb = Y + (((size_t)b * HW + h) * HW) * FOUT;
    #pragma unroll
    for (int mt = 0; mt < 4; ++mt)
        #pragma unroll
        for (int rg = 0; rg < 2; ++rg) {
            const int m = mw + mt * 16 + rg * 8 + (lane >> 2);
            float* yr = Yb + (size_t)m * FOUT + nw + (lane & 3) * 2;
            #pragma unroll
            for (int nt = 0; nt < 8; ++nt) {
                float2 v;
                v.x = acc[mt][nt][rg * 2];
                v.y = acc[mt][nt][rg * 2 + 1];
                *(float2*)(yr + nt * 8) = v;
            }
        }
    #undef ISSUE_A
    #undef ISSUE_B
}

// ---------------------------------------------------------------------------
extern "C" void kernel_launch(void* const* d_in, const int* in_sizes, int n_in,
                              void* d_out, int out_size) {
    const float* x     = (const float*)d_in[0];   // (8,128,128,128)
    const float* style = (const float*)d_in[1];   // (8,128)
    const float* kern  = (const float*)d_in[2];   // (3,3,128,128)
    float* y = (float*)d_out;

    cudaFuncSetAttribute(mdconv_hmma_kernel,
                         cudaFuncAttributeMaxDynamicSharedMemorySize, SMEM_TOTAL);

    // wprep first: overlaps its latency-bound loads with split_x's stream.
    wprep_kernel<<<dim3(FOUT, BATCH), 128>>>(style, kern);
    split_x_kernel<<<(BATCH * HW * HW * CIN) / 16 / 256, 256>>>(x);
    mdconv_hmma_kernel<<<dim3(HW, BATCH), 128, SMEM_TOTAL>>>(y);
}

// round 15
// speedup vs baseline: 1.1730x; 1.0241x over previous
#include <cuda_runtime.h>
#include <cuda_fp16.h>
#include <cstdint>

// StyleGAN2 modulated+demodulated conv on GB300 (sm_103 base target -> HMMA).
// x: (8,128,128,128) NHWC fp32, style: (8,128), kernel: (3,3,128,128) -> NHWC fp32
//
// Single-product fp16 GEMM: Y = fp16(X) * fp16(W_mod_demod), fp32 accum.
// K0 wprep: demod scale + modulate -> fp16 W, layout [b][f][k]
// K1 gemm : per (h,b) CTA: M=128 (w), N=128 (f), K=1152.
//   NO separate X split kernel: A windows are cp.async'd as fp32 into an
//   unswizzled staging buffer, then converted in-smem (fp32->fp16, SW128)
//   once per (dy, c-half) stage (6 stages; 3 dx taps via smem row offset).
//   B: 18 chunks of 64, ring-2 cp.async, wait_group(0) per iter.
//   4 warps, warp tile 64x64, smem 101376 -> 2 CTAs/SM.

#define HW    128
#define CIN   128
#define FOUT  128
#define BATCH 8
#define KK    1152
#define NCH   18

__device__ __half g_wh[BATCH * FOUT * KK];

// ---------------- asm helpers ----------------
__device__ __forceinline__ uint32_t smem_u32(const void* p) {
    uint32_t a;
    asm("{ .reg .u64 t; cvta.to.shared.u64 t, %1; cvt.u32.u64 %0, t; }"
        : "=r"(a) : "l"(p));
    return a;
}
__device__ __forceinline__ void ldsm4(uint32_t* r, uint32_t addr) {
    asm volatile("ldmatrix.sync.aligned.m8n8.x4.shared.b16 {%0,%1,%2,%3}, [%4];"
                 : "=r"(r[0]), "=r"(r[1]), "=r"(r[2]), "=r"(r[3]) : "r"(addr));
}
__device__ __forceinline__ void mma_f16(float* c, const uint32_t* a, const uint32_t* b) {
    asm volatile(
        "mma.sync.aligned.m16n8k16.row.col.f32.f16.f16.f32 "
        "{%0,%1,%2,%3}, {%4,%5,%6,%7}, {%8,%9}, {%0,%1,%2,%3};"
        : "+f"(c[0]), "+f"(c[1]), "+f"(c[2]), "+f"(c[3])
        : "r"(a[0]), "r"(a[1]), "r"(a[2]), "r"(a[3]), "r"(b[0]), "r"(b[1]));
}
__device__ __forceinline__ void cp_async16z(uint32_t saddr, const void* gaddr,
                                            uint32_t src_size) {
    asm volatile("cp.async.cg.shared.global [%0], [%1], 16, %2;"
                 :: "r"(saddr), "l"(gaddr), "r"(src_size));
}
__device__ __forceinline__ void cp_async16(uint32_t saddr, const void* gaddr) {
    asm volatile("cp.async.cg.shared.global [%0], [%1], 16;"
                 :: "r"(saddr), "l"(gaddr));
}
__device__ __forceinline__ void cp_commit() { asm volatile("cp.async.commit_group;"); }
#define CP_WAIT(n) asm volatile("cp.async.wait_group %0;" :: "n"(n) : "memory")

// ---------------------------------------------------------------------------
// K0: fused demod scale + modulate -> fp16, layout [b][f][k].
// ---------------------------------------------------------------------------
__global__ void wprep_kernel(const float* __restrict__ style,
                             const float* __restrict__ kern) {
    const int f = blockIdx.x, b = blockIdx.y, c = threadIdx.x;
    const float st = style[b * CIN + c] + 1.0f;
    float wv[9];
    float ss = 0.0f;
    #pragma unroll
    for (int p = 0; p < 9; ++p) {
        float w = kern[(p * 128 + c) * 128 + f] * st;
        wv[p] = w;
        ss = fmaf(w, w, ss);
    }
    __shared__ float red[128];
    red[c] = ss;
    __syncthreads();
    #pragma unroll
    for (int s = 64; s > 0; s >>= 1) {
        if (c < s) red[c] += red[c + s];
        __syncthreads();
    }
    const float scale = rsqrtf(red[0] + 1e-8f);
    const size_t base = (size_t)(b * 128 + f) * KK;
    #pragma unroll
    for (int p = 0; p < 9; ++p)
        g_wh[base + p * 128 + c] = __float2half_rn(wv[p] * scale);
}

// ---------------------------------------------------------------------------
// K1: HMMA implicit GEMM; A converted fp32->fp16 in-smem.
// grid (128 h, 8 b) x 128 threads (4 warps), 2 CTAs/SM.
// Warps 2(m) x 2(n), warp tile 64x64.
// SMEM: A fp16 2x17408 | staging fp32 33792 | B 2x16384  = 101376.
// ---------------------------------------------------------------------------
#define ABUF_BYTES 17408
#define STG_BYTES  33792                    // 130 rows x 256B = 33280, padded
#define BBUF_BYTES 16384
#define SMEM_STG   (2 * ABUF_BYTES)         // 34816
#define SMEM_B0    (SMEM_STG + STG_BYTES)   // 68608
#define SMEM_TOTAL (SMEM_B0 + 2 * BBUF_BYTES) // 101376

__global__ __launch_bounds__(128, 2)
void mdconv_hmma_kernel(const float* __restrict__ X, float* __restrict__ Y) {
    extern __shared__ __align__(1024) char smem[];
    const uint32_t sb  = smem_u32(smem);
    const int tid  = threadIdx.x;
    const int wid  = tid >> 5;
    const int lane = tid & 31;
    const int h = blockIdx.x;
    const int b = blockIdx.y;

    const int mw = (wid >> 1) * 64;     // warp m offset
    const int nw = (wid & 1) * 64;      // warp n offset

    const float* xb   = X + (size_t)b * HW * HW * CIN;
    const __half* wh_b = g_wh + (size_t)b * FOUT * KK;

    // ---- ldmatrix per-lane invariants ----
    const int arow_l = (lane & 7) + ((lane >> 3) & 1) * 8;
    const int akb_l  = ((lane >> 4) & 1) * 16;
    const int brow_l = (lane & 7) + ((lane >> 4) & 1) * 8;
    const int bkb_l  = ((lane >> 3) & 1) * 16;

    int aRowBase[4];
    #pragma unroll
    for (int mt = 0; mt < 4; ++mt) aRowBase[mt] = mw + mt * 16 + arow_l;
    uint32_t bRowOff[4], bXor[4];
    #pragma unroll
    for (int np = 0; np < 4; ++np) {
        const int row = nw + np * 16 + brow_l;
        bRowOff[np] = (uint32_t)row * 128;
        bXor[np]    = (uint32_t)((row & 7) * 16);
    }

    float acc[4][8][4];
    #pragma unroll
    for (int i = 0; i < 4; ++i)
        #pragma unroll
        for (int j = 0; j < 8; ++j)
            #pragma unroll
            for (int q = 0; q < 4; ++q) acc[i][j][q] = 0.0f;

    // Stage s_: fp32 window (130 rows w=-1..128, 64 ch c0..c0+63) -> staging.
    // 130 rows x 16 segs(16B) = 2080 = 16*128 + 32.
    #define ISSUE_STG(s_)                                                     \
    {                                                                         \
        const int dy_ = (s_) / 2 - 1;                                         \
        const int c0_ = ((s_) & 1) * 64;                                      \
        const int hh_ = h + dy_;                                              \
        const bool hok_ = (unsigned)hh_ < HW;                                 \
        _Pragma("unroll")                                                     \
        for (int t = 0; t < 16; ++t) {                                        \
            const int u = tid + 128 * t;                                      \
            const int row = u >> 4, seg = u & 15;                             \
            const int wq = row - 1;                                           \
            const bool ok = hok_ && ((unsigned)wq < HW);                      \
            const float* ga = ok                                              \
                ? xb + (((size_t)hh_ * HW + wq) << 7) + c0_ + seg * 4         \
                : xb;                                                         \
            cp_async16z(sb + SMEM_STG + row * 256 + seg * 16, ga,             \
                        ok ? 16u : 0u);                                       \
        }                                                                     \
        if (tid < 32) {                                                       \
            const int u = 2048 + tid;                                         \
            const int row = u >> 4, seg = u & 15;                             \
            const int wq = row - 1;                                           \
            const bool ok = hok_ && ((unsigned)wq < HW);                      \
            const float* ga = ok                                              \
                ? xb + (((size_t)hh_ * HW + wq) << 7) + c0_ + seg * 4         \
                : xb;                                                         \
            cp_async16z(sb + SMEM_STG + row * 256 + seg * 16, ga,             \
                        ok ? 16u : 0u);                                       \
        }                                                                     \
    }

    // Convert staging fp32 -> A fp16 buffer (s_&1), SW128 swizzled.
    // 130 rows x 8 out-segs(16B) = 1040 = 8*128 + 16.
    #define CONVERT_ONE(u_)                                                   \
    {                                                                         \
        const int row = (u_) >> 3, seg = (u_) & 7;                            \
        const float4 f0 = *(const float4*)(smem + SMEM_STG + row * 256        \
                                           + seg * 32);                       \
        const float4 f1 = *(const float4*)(smem + SMEM_STG + row * 256        \
                                           + seg * 32 + 16);                  \
        __half2 q0 = __floats2half2_rn(f0.x, f0.y);                           \
        __half2 q1 = __floats2half2_rn(f0.z, f0.w);                           \
        __half2 q2 = __floats2half2_rn(f1.x, f1.y);                           \
        __half2 q3 = __floats2half2_rn(f1.z, f1.w);                           \
        uint4 o = make_uint4(*(uint32_t*)&q0, *(uint32_t*)&q1,                \
                             *(uint32_t*)&q2, *(uint32_t*)&q3);               \
        *(uint4*)(smem + abase_ + row * 128                                   \
                  + ((seg * 16) ^ ((row & 7) * 16))) = o;                     \
    }
    #define CONVERT(s_)                                                       \
    {                                                                         \
        const uint32_t abase_ = (uint32_t)((s_) & 1) * ABUF_BYTES;            \
        _Pragma("unroll")                                                     \
        for (int t = 0; t < 8; ++t) { CONVERT_ONE(tid + 128 * t); }           \
        if (tid < 16) { CONVERT_ONE(1024 + tid); }                            \
    }

    #define ISSUE_B(kc_)                                                      \
    {                                                                         \
        const uint32_t bbuf = sb + SMEM_B0                                    \
                            + (uint32_t)((kc_) & 1) * BBUF_BYTES;             \
        const int s_  = (kc_) / 3;                                            \
        const int p_  = (s_ / 2) * 3 + (kc_) % 3;                             \
        const int c0_ = (s_ & 1) * 64;                                        \
        _Pragma("unroll")                                                     \
        for (int t = 0; t < 8; ++t) {                                         \
            const int u = tid + 128 * t;                                      \
            const int f_ = u >> 3, seg = u & 7;                               \
            cp_async16(bbuf + f_ * 128 + ((seg * 16) ^ ((f_ & 7) * 16)),      \
                       wh_b + (size_t)f_ * KK + p_ * 128 + c0_ + seg * 8);    \
        }                                                                     \
    }

    // ---- prologue: staging(0) + B(0); drain; convert stage 0 ----
    ISSUE_STG(0); ISSUE_B(0); cp_commit();
    CP_WAIT(0);
    __syncthreads();
    CONVERT(0);
    __syncthreads();

    for (int kc = 0; kc < NCH; ++kc) {
        // wait(0): B(kc) (issued at iter kc-1) + any staging complete.
        CP_WAIT(0);
        __syncthreads();

        const int s    = kc / 3;
        const int dxp1 = kc % 3;

        // Issue after the barrier. B(kc+1) -> buf (kc+1)&1 (held B(kc-1),
        // last read iter kc-1, fenced by the sync above). staging overwrite
        // at kc=3s: its convert reads happened at iter 3s-1, fenced.
        if (kc % 3 == 0 && (s + 1) < 6) ISSUE_STG(s + 1);
        if (kc + 1 < NCH) ISSUE_B(kc + 1);
        cp_commit();

        // Convert stage s+1 at kc=3s+2: staging committed at 3s, drained by
        // wait(0) at 3s+1. Writes A buf (s+1)&1, last read at iter 3s-1;
        // first read at iter 3s+3 (after that iter's sync).
        if (kc % 3 == 2 && (s + 1) < 6) CONVERT(s + 1);

        const uint32_t abuf = sb + (uint32_t)(s & 1) * ABUF_BYTES;
        const uint32_t bbuf = sb + SMEM_B0 + (uint32_t)(kc & 1) * BBUF_BYTES;

        #pragma unroll
        for (int ks = 0; ks < 4; ++ks) {
            uint32_t Af[4][4], Bf[4][4];
            #pragma unroll
            for (int mt = 0; mt < 4; ++mt) {
                const int row = aRowBase[mt] + dxp1;
                const uint32_t off = (uint32_t)row * 128
                    + ((uint32_t)(ks * 32 + akb_l) ^ ((row & 7) * 16));
                ldsm4(Af[mt], abuf + off);
            }
            #pragma unroll
            for (int np = 0; np < 4; ++np)
                ldsm4(Bf[np], bbuf + bRowOff[np]
                      + ((uint32_t)(ks * 32 + bkb_l) ^ bXor[np]));
            #pragma unroll
            for (int mt = 0; mt < 4; ++mt)
                #pragma unroll
                for (int np = 0; np < 4; ++np) {
                    mma_f16(acc[mt][np * 2],     Af[mt], &Bf[np][0]);
                    mma_f16(acc[mt][np * 2 + 1], Af[mt], &Bf[np][2]);
                }
        }
    }

    // ---- epilogue: direct STG ----
    float* Yb = Y + (((size_t)b * HW + h) * HW) * FOUT;
    #pragma unroll
    for (int mt = 0; mt < 4; ++mt)
        #pragma unroll
        for (int rg = 0; rg < 2; ++rg) {
            const int m = mw + mt * 16 + rg * 8 + (lane >> 2);
            float* yr = Yb + (size_t)m * FOUT + nw + (lane & 3) * 2;
            #pragma unroll
            for (int nt = 0; nt < 8; ++nt) {
                float2 v;
                v.x = acc[mt][nt][rg * 2];
                v.y = acc[mt][nt][rg * 2 + 1];
                *(float2*)(yr + nt * 8) = v;
            }
        }
    #undef ISSUE_STG
    #undef CONVERT_ONE
    #undef CONVERT
    #undef ISSUE_B
}

// ---------------------------------------------------------------------------
extern "C" void kernel_launch(void* const* d_in, const int* in_sizes, int n_in,
                              void* d_out, int out_size) {
    const float* x     = (const float*)d_in[0];   // (8,128,128,128)
    const float* style = (const float*)d_in[1];   // (8,128)
    const float* kern  = (const float*)d_in[2];   // (3,3,128,128)
    float* y = (float*)d_out;

    cudaFuncSetAttribute(mdconv_hmma_kernel,
                         cudaFuncAttributeMaxDynamicSharedMemorySize, SMEM_TOTAL);

    wprep_kernel<<<dim3(FOUT, BATCH), 128>>>(style, kern);
    mdconv_hmma_kernel<<<dim3(HW, BATCH), 128, SMEM_TOTAL>>>(x, y);
}